// round 3
// baseline (speedup 1.0000x reference)
#include <cuda_runtime.h>

// DeformConv: B=8, C=64, H=W=96, COUT=64, 3x3, stride=1, pad=1, dil=1
// out[b,o,h,w] = sum_{c,k} weight[o,c,k] * bilinear(x[b,c], p(k,h,w) + offset[b,k,:,h,w])

#define B_    8
#define C_    64
#define H_    96
#define W_    96
#define CO_   64
#define K2_   9
#define NPIX  (H_ * W_)      // 9216
#define TILE  64             // output pixels per block
#define NTHREADS 256

// Pre-transposed weight: wT[k][c][o] = weight[o][c][k]  (147 KB scratch)
__device__ __align__(16) float g_wT[K2_ * C_ * CO_];

__global__ void wtrans_kernel(const float* __restrict__ w) {
    int idx = blockIdx.x * 256 + threadIdx.x;           // 0 .. 36863
    if (idx >= CO_ * C_ * K2_) return;
    int o   = idx / (C_ * K2_);
    int rem = idx % (C_ * K2_);
    int c   = rem / K2_;
    int k   = rem % K2_;
    g_wT[(k * C_ + c) * CO_ + o] = w[idx];
}

// ---- f32x2 packed math (2 fp32 FMAs per instruction) ----
__device__ __forceinline__ unsigned long long pack2(float a, float b) {
    unsigned long long r;
    asm("mov.b64 %0, {%1, %2};" : "=l"(r) : "f"(a), "f"(b));
    return r;
}
__device__ __forceinline__ void fma2(unsigned long long& d,
                                     unsigned long long a,
                                     unsigned long long b) {
    asm("fma.rn.f32x2 %0, %1, %2, %0;" : "+l"(d) : "l"(a), "l"(b));
}
__device__ __forceinline__ void unpack2(unsigned long long v, float& a, float& b) {
    asm("mov.b64 {%0, %1}, %2;" : "=f"(a), "=f"(b) : "l"(v));
}

__global__ __launch_bounds__(NTHREADS) void dconv_kernel(
    const float* __restrict__ x,
    const float* __restrict__ off,
    float* __restrict__ out)
{
    __shared__ __align__(16) float cols[C_][TILE];   // 16 KB: column tile for current tap
    __shared__ __align__(16) float wsm[C_][CO_];     // 16 KB: weight slice wsm[c][o]
    __shared__ int   s_o0[TILE], s_o1[TILE], s_o2[TILE], s_o3[TILE];
    __shared__ float s_w0[TILE], s_w1[TILE], s_w2[TILE], s_w3[TILE];

    const int t = threadIdx.x;
    const int b = blockIdx.y;
    const int tile_base = blockIdx.x * TILE;

    // GEMM micro-tile assignment: 16 px-groups x 16 o-groups
    const int tx = t & 15;    // pixels tx*4 .. tx*4+3
    const int ty = t >> 4;    // outputs ty*4 .. ty*4+3

    unsigned long long acc[4][2];
#pragma unroll
    for (int i = 0; i < 4; i++) { acc[i][0] = 0ull; acc[i][1] = 0ull; }

    const float* xb = x + (size_t)b * C_ * NPIX;

    for (int k = 0; k < K2_; k++) {
        __syncthreads();   // protect cols/wsm/coord arrays from previous iteration's readers

        // --- stage weight slice for this tap (coalesced float4) ---
        {
            const float4* wk = (const float4*)(g_wT + k * C_ * CO_);
            float4* wd = (float4*)&wsm[0][0];
#pragma unroll
            for (int i = 0; i < 4; i++)
                wd[t + NTHREADS * i] = wk[t + NTHREADS * i];
        }

        // --- per-pixel bilinear coordinates for this tap ---
        if (t < TILE) {
            int p  = tile_base + t;
            int ho = p / W_;
            int wo = p % W_;
            float offy = off[((size_t)b * (2 * K2_) + 2 * k    ) * NPIX + p];
            float offx = off[((size_t)b * (2 * K2_) + 2 * k + 1) * NPIX + p];
            float py = (float)(ho - 1 + k / 3) + offy;
            float px = (float)(wo - 1 + k % 3) + offx;
            float y0f = floorf(py), x0f = floorf(px);
            float ly = py - y0f,    lx = px - x0f;
            int y0 = (int)y0f, x0 = (int)x0f;
            int y1 = y0 + 1,   x1 = x0 + 1;
            float vy0 = (y0 >= 0 && y0 < H_) ? 1.f : 0.f;
            float vy1 = (y1 >= 0 && y1 < H_) ? 1.f : 0.f;
            float vx0 = (x0 >= 0 && x0 < W_) ? 1.f : 0.f;
            float vx1 = (x1 >= 0 && x1 < W_) ? 1.f : 0.f;
            int y0c = min(max(y0, 0), H_ - 1), y1c = min(max(y1, 0), H_ - 1);
            int x0c = min(max(x0, 0), W_ - 1), x1c = min(max(x1, 0), W_ - 1);
            s_o0[t] = y0c * W_ + x0c;  s_w0[t] = (1.f - ly) * (1.f - lx) * vy0 * vx0;
            s_o1[t] = y0c * W_ + x1c;  s_w1[t] = (1.f - ly) * lx         * vy0 * vx1;
            s_o2[t] = y1c * W_ + x0c;  s_w2[t] = ly         * (1.f - lx) * vy1 * vx0;
            s_o3[t] = y1c * W_ + x1c;  s_w3[t] = ly         * lx         * vy1 * vx1;
        }
        __syncthreads();

        // --- gather column tile: cols[c][p] (coords cached in regs across c) ---
        {
            const int p  = t & 63;
            const int cg = t >> 6;   // 0..3 -> channels cg*16 .. cg*16+15
            const int o0 = s_o0[p], o1 = s_o1[p], o2 = s_o2[p], o3 = s_o3[p];
            const float w0 = s_w0[p], w1 = s_w1[p], w2 = s_w2[p], w3 = s_w3[p];
            const float* xc = xb + (size_t)(cg * 16) * NPIX;
#pragma unroll
            for (int i = 0; i < 16; i++) {
                float v = w0 * __ldg(xc + o0) + w1 * __ldg(xc + o1)
                        + w2 * __ldg(xc + o2) + w3 * __ldg(xc + o3);
                cols[cg * 16 + i][p] = v;
                xc += NPIX;
            }
        }
        __syncthreads();

        // --- GEMM step: acc[o][p] += wsm[c][o] * cols[c][p], c = 0..63 ---
#pragma unroll 16
        for (int r = 0; r < C_; r++) {
            float4 c4 = *(const float4*)&cols[r][tx * 4];
            float4 w4 = *(const float4*)&wsm[r][ty * 4];
            unsigned long long c01 = pack2(c4.x, c4.y);
            unsigned long long c23 = pack2(c4.z, c4.w);
            unsigned long long wp;
            wp = pack2(w4.x, w4.x); fma2(acc[0][0], wp, c01); fma2(acc[0][1], wp, c23);
            wp = pack2(w4.y, w4.y); fma2(acc[1][0], wp, c01); fma2(acc[1][1], wp, c23);
            wp = pack2(w4.z, w4.z); fma2(acc[2][0], wp, c01); fma2(acc[2][1], wp, c23);
            wp = pack2(w4.w, w4.w); fma2(acc[3][0], wp, c01); fma2(acc[3][1], wp, c23);
        }
    }

    // --- epilogue: float4 stores, fully coalesced along pixel dim ---
#pragma unroll
    for (int oi = 0; oi < 4; oi++) {
        int o = ty * 4 + oi;
        float4 v;
        unpack2(acc[oi][0], v.x, v.y);
        unpack2(acc[oi][1], v.z, v.w);
        *(float4*)(out + ((size_t)(b * CO_ + o)) * NPIX + tile_base + tx * 4) = v;
    }
}

extern "C" void kernel_launch(void* const* d_in, const int* in_sizes, int n_in,
                              void* d_out, int out_size) {
    const float* x   = (const float*)d_in[0];   // (8, 64, 96, 96)
    const float* off = (const float*)d_in[1];   // (8, 18, 96, 96)
    const float* w   = (const float*)d_in[2];   // (64, 64, 3, 3)
    float* out = (float*)d_out;                 // (8, 64, 96, 96)

    wtrans_kernel<<<(CO_ * C_ * K2_ + 255) / 256, 256>>>(w);

    dim3 grid(NPIX / TILE, B_);                 // (144, 8) = 1152 blocks
    dconv_kernel<<<grid, NTHREADS>>>(x, off, out);
}